// round 6
// baseline (speedup 1.0000x reference)
#include <cuda_runtime.h>
#include <cuda_bf16.h>

// QuantumLayer analytic collapse:
//   out[b,i] = prod_{c <= i, ((i-c) & (L-1)) == 0} cos(x[b,c])
// RZ layers are unit-modulus diagonal phases -> cancel in |.|^2; the CNOT
// chain is the GF(2) prefix-sum matrix M; Z_i after L layers pulls back to
// the parity set = row i of M^L, (M^L)_{ic} = C(i-c+L-1, L-1) mod 2, odd iff
// ((i-c) & (L-1)) == 0 (Kummer). Product measure -> expectation factorizes
// into prod cos(x_c). q_weights is mathematically irrelevant to the output.
//
// Row recurrence: p[j] = cos(x[j]); p[j] *= p[j-L] for j >= L (power-of-2 L).

constexpr int N = 10;        // wires (q_weights.shape[1]); N*4 = 40 bytes/row
constexpr int TPB = 64;      // one thread per row

template<int L>
__global__ __launch_bounds__(TPB)
void quantum_row_kernel(const float* __restrict__ x,
                        float* __restrict__ out, int B) {
    int b = blockIdx.x * TPB + threadIdx.x;
    if (b >= B) return;

    // Row offset = 40*b bytes -> always 8-byte aligned: float2 loads/stores.
    const float2* rx = (const float2*)(x + b * N);
    float p[N];
    #pragma unroll
    for (int h = 0; h < N / 2; h++) {      // 5 independent LDG.64
        float2 t = __ldg(rx + h);
        p[2 * h]     = __cosf(t.x);        // 10 independent MUFU.COS
        p[2 * h + 1] = __cosf(t.y);
    }
    #pragma unroll
    for (int j = L; j < N; j++)            // stride-L suffix product
        p[j] *= p[j - L];

    float2* ro = (float2*)(out + b * N);
    #pragma unroll
    for (int h = 0; h < N / 2; h++) {      // 5 STG.64
        float2 t;
        t.x = p[2 * h];
        t.y = p[2 * h + 1];
        ro[h] = t;
    }
}

// Generic fallback (any L): Kummer mask rule, one thread per output element.
__global__ __launch_bounds__(256)
void quantum_generic_kernel(const float* __restrict__ x,
                            float* __restrict__ out,
                            int total, int Lm1) {
    int t = blockIdx.x * blockDim.x + threadIdx.x;
    if (t >= total) return;
    int b = t / N;
    int i = t - b * N;
    const float* row = x + b * N;
    float p = 1.0f;
    #pragma unroll
    for (int c = i; c >= 0; --c)
        if (((i - c) & Lm1) == 0)
            p *= __cosf(__ldg(row + c));
    out[t] = p;
}

extern "C" void kernel_launch(void* const* d_in, const int* in_sizes, int n_in,
                              void* d_out, int out_size) {
    const float* x = (const float*)d_in[0];
    // d_in[1] = q_weights: unused (phases cancel in probabilities)
    const int L = in_sizes[1] / N;   // layers
    const int B = out_size / N;      // batch rows
    float* out = (float*)d_out;

    const int blocks = (B + TPB - 1) / TPB;

    switch (L) {
        case 1: quantum_row_kernel<1><<<blocks, TPB>>>(x, out, B); break;
        case 2: quantum_row_kernel<2><<<blocks, TPB>>>(x, out, B); break;
        case 4: quantum_row_kernel<4><<<blocks, TPB>>>(x, out, B); break;
        case 8: quantum_row_kernel<8><<<blocks, TPB>>>(x, out, B); break;
        default: {
            int total = out_size;
            quantum_generic_kernel<<<(total + 255) / 256, 256>>>(x, out, total, L - 1);
        }
    }
}

// round 7
// speedup vs baseline: 4.4848x; 4.4848x over previous
#include <cuda_runtime.h>
#include <cuda_bf16.h>

// QuantumLayer analytic collapse:
//   out[b,i] = prod_{c <= i, ((i-c) & (L-1)) == 0} cos(x[b,c])
// RZ layers are unit-modulus diagonal phases -> cancel in |.|^2; the CNOT
// chain is the GF(2) prefix-sum matrix M; Z_i after L layers pulls back to
// the parity set = row i of M^L, (M^L)_{ic} = C(i-c+L-1, L-1) mod 2, odd iff
// ((i-c) & (L-1)) == 0 (Kummer). Product measure -> the parity expectation
// factorizes into prod cos(x_c). q_weights is mathematically irrelevant.
//
// Perf note (R6 lesson): kernel time is pinned at ~4us = launch overhead +
// one DRAM round trip; wall-clock replay time inflates when grid < 148
// (sm_103a low-grid throttle/DVFS). Keep grid >= 148.

constexpr int N = 10;   // wires (q_weights.shape[1])

// Power-of-2 L: membership is stride-L. One thread per output element,
// <= ceil(N/L) independent predicated loads + MUFU cos, no sync, no guard
// on the exact-fit path.
template<int L, bool EXACT>
__global__ __launch_bounds__(256)
void quantum_elem_kernel(const float* __restrict__ x,
                         float* __restrict__ out, int total) {
    int t = blockIdx.x * blockDim.x + threadIdx.x;
    if (!EXACT && t >= total) return;
    int b = t / N;            // constexpr divisor -> mul/shift, no IDIV
    int i = t - b * N;
    const float* row = x + b * N;

    float p = __cosf(__ldg(row + i));
    #pragma unroll
    for (int k = 1; k * L < N; k++) {
        int c = i - k * L;
        if (c >= 0) p *= __cosf(__ldg(row + c));
    }
    out[t] = p;
}

// Generic fallback: any L, Kummer mask rule.
__global__ __launch_bounds__(256)
void quantum_generic_kernel(const float* __restrict__ x,
                            float* __restrict__ out,
                            int total, int Lm1) {
    int t = blockIdx.x * blockDim.x + threadIdx.x;
    if (t >= total) return;
    int b = t / N;
    int i = t - b * N;
    const float* row = x + b * N;
    float p = 1.0f;
    #pragma unroll
    for (int c = i; c >= 0; --c)
        if (((i - c) & Lm1) == 0)
            p *= __cosf(__ldg(row + c));
    out[t] = p;
}

extern "C" void kernel_launch(void* const* d_in, const int* in_sizes, int n_in,
                              void* d_out, int out_size) {
    const float* x = (const float*)d_in[0];
    // d_in[1] = q_weights: unused (phases cancel in probabilities)
    const int L = in_sizes[1] / N;   // layers
    const int total = out_size;      // B * N
    float* out = (float*)d_out;

    const int threads = 256;
    const int blocks = (total + threads - 1) / threads;
    const bool exact = (total % threads) == 0;

    #define LAUNCH(LV)                                                        \
        do {                                                                  \
            if (exact)                                                        \
                quantum_elem_kernel<LV, true><<<blocks, threads>>>(x, out, total);  \
            else                                                              \
                quantum_elem_kernel<LV, false><<<blocks, threads>>>(x, out, total); \
        } while (0)

    switch (L) {
        case 1: LAUNCH(1); break;
        case 2: LAUNCH(2); break;
        case 4: LAUNCH(4); break;
        case 8: LAUNCH(8); break;
        default:
            quantum_generic_kernel<<<blocks, threads>>>(x, out, total, L - 1);
    }
    #undef LAUNCH
}